// round 1
// baseline (speedup 1.0000x reference)
#include <cuda_runtime.h>
#include <math.h>

#define LSE_EPS 1e-5f

// Folded weights: [0:16) W1f (o-major, o*4+c), [16:20) b1f, [20:52) W2f (j*4+o), [52:60) b2f
__device__ float g_fold[60];

__global__ void fold_weights_kernel(
    const float* __restrict__ W1, const float* __restrict__ g1,
    const float* __restrict__ b1, const float* __restrict__ m1,
    const float* __restrict__ v1,
    const float* __restrict__ W2, const float* __restrict__ g2,
    const float* __restrict__ b2, const float* __restrict__ m2,
    const float* __restrict__ v2)
{
    int t = threadIdx.x;
    if (t < 4) {
        float s = g1[t] * rsqrtf(v1[t] + LSE_EPS);
        g_fold[16 + t] = b1[t] - m1[t] * s;
        #pragma unroll
        for (int c = 0; c < 4; ++c) g_fold[t * 4 + c] = W1[t * 4 + c] * s;
    }
    if (t < 8) {
        float s = g2[t] * rsqrtf(v2[t] + LSE_EPS);
        g_fold[52 + t] = b2[t] - m2[t] * s;
        #pragma unroll
        for (int c = 0; c < 4; ++c) g_fold[20 + t * 4 + c] = W2[t * 4 + c] * s;
    }
}

// Each thread handles 4 consecutive neighbors (k) of one (b,n) point.
// 4 threads per (b,n) group; K = 16.
__global__ __launch_bounds__(256) void lse_main_kernel(
    const float* __restrict__ coords,        // (BN, 3)
    const float* __restrict__ nbr,           // (BN, 16, 3)
    float* __restrict__ out,                 // (BN, 16, 8)
    int total_bn)
{
    __shared__ float sw[60];
    if (threadIdx.x < 60) sw[threadIdx.x] = g_fold[threadIdx.x];
    __syncthreads();

    int t = blockIdx.x * blockDim.x + threadIdx.x;
    int bn = t >> 2;
    if (bn >= total_bn) return;
    int k0 = (t & 3) * 4;   // 0,4,8,12

    // Stage folded weights into registers (fully unrolled -> regs)
    float fw1[16], fb1[4], fw2[32], fb2[8];
    #pragma unroll
    for (int i = 0; i < 16; ++i) fw1[i] = sw[i];
    #pragma unroll
    for (int i = 0; i < 4; ++i)  fb1[i] = sw[16 + i];
    #pragma unroll
    for (int i = 0; i < 32; ++i) fw2[i] = sw[20 + i];
    #pragma unroll
    for (int i = 0; i < 8; ++i)  fb2[i] = sw[52 + i];

    // Center coords (broadcast among the 4 threads of this bn; L1-resident)
    const float* cp = coords + (size_t)bn * 3;
    float cx = __ldg(cp + 0);
    float cy = __ldg(cp + 1);
    float cz = __ldg(cp + 2);

    // 12 neighbor floats = 3 aligned float4 (base = bn*192B + k0*12B, 16B aligned)
    const float4* np = reinterpret_cast<const float4*>(nbr + (size_t)bn * 48 + (size_t)k0 * 3);
    float4 q0 = np[0];
    float4 q1 = np[1];
    float4 q2 = np[2];
    float nb[12] = { q0.x, q0.y, q0.z, q0.w,
                     q1.x, q1.y, q1.z, q1.w,
                     q2.x, q2.y, q2.z, q2.w };

    float* op = out + (size_t)bn * 128 + (size_t)k0 * 8;

    #pragma unroll
    for (int k = 0; k < 4; ++k) {
        float rx = nb[3 * k + 0] - cx;
        float ry = nb[3 * k + 1] - cy;
        float rz = nb[3 * k + 2] - cz;
        float dist = sqrtf(rx * rx + ry * ry + rz * rz);

        float h[4];
        #pragma unroll
        for (int o = 0; o < 4; ++o) {
            float acc = fb1[o];
            acc = fmaf(fw1[o * 4 + 0], rx, acc);
            acc = fmaf(fw1[o * 4 + 1], ry, acc);
            acc = fmaf(fw1[o * 4 + 2], rz, acc);
            acc = fmaf(fw1[o * 4 + 3], dist, acc);
            h[o] = fmaxf(acc, 0.0f);
        }

        float o8[8];
        #pragma unroll
        for (int j = 0; j < 8; ++j) {
            float acc = fb2[j];
            acc = fmaf(fw2[j * 4 + 0], h[0], acc);
            acc = fmaf(fw2[j * 4 + 1], h[1], acc);
            acc = fmaf(fw2[j * 4 + 2], h[2], acc);
            acc = fmaf(fw2[j * 4 + 3], h[3], acc);
            o8[j] = fmaxf(acc, 0.0f);
        }

        float4* ov = reinterpret_cast<float4*>(op + (size_t)k * 8);
        ov[0] = make_float4(o8[0], o8[1], o8[2], o8[3]);
        ov[1] = make_float4(o8[4], o8[5], o8[6], o8[7]);
    }
}

extern "C" void kernel_launch(void* const* d_in, const int* in_sizes, int n_in,
                              void* d_out, int out_size)
{
    const float* coords = (const float*)d_in[0];   // (B,N,3)
    const float* nbr    = (const float*)d_in[1];   // (B,N,K,3)
    const float* W1 = (const float*)d_in[2];
    const float* g1 = (const float*)d_in[3];
    const float* b1 = (const float*)d_in[4];
    const float* m1 = (const float*)d_in[5];
    const float* v1 = (const float*)d_in[6];
    const float* W2 = (const float*)d_in[7];
    const float* g2 = (const float*)d_in[8];
    const float* b2 = (const float*)d_in[9];
    const float* m2 = (const float*)d_in[10];
    const float* v2 = (const float*)d_in[11];
    float* out = (float*)d_out;

    int total_bn = in_sizes[0] / 3;               // B*N = 131072
    int threads  = total_bn * 4;                  // 4 threads per bn (K/4 each)
    int block = 256;
    int grid = (threads + block - 1) / block;

    fold_weights_kernel<<<1, 32>>>(W1, g1, b1, m1, v1, W2, g2, b2, m2, v2);
    lse_main_kernel<<<grid, block>>>(coords, nbr, out, total_bn);
}

// round 2
// speedup vs baseline: 1.3385x; 1.3385x over previous
#include <cuda_runtime.h>
#include <math.h>

#define LSE_EPS 1e-5f

// SMEM weight layout: [0:16) W1f (o*4+c), [16:20) b1f, [20:52) W2f (j*4+c), [52:60) b2f
// Per-warp transpose buffers after weights.

#define WB_STRIDE 1152              // bytes per warp buffer (A at +0: 512B, B at +576: 512B)
#define NWARPS 8                    // 256-thread blocks

__global__ __launch_bounds__(256, 3) void lse_fused_kernel(
    const float* __restrict__ coords,        // (BN, 3)
    const float* __restrict__ nbr,           // (BN, 16, 3)
    const float* __restrict__ W1, const float* __restrict__ g1,
    const float* __restrict__ b1, const float* __restrict__ m1,
    const float* __restrict__ v1,
    const float* __restrict__ W2, const float* __restrict__ g2,
    const float* __restrict__ b2, const float* __restrict__ m2,
    const float* __restrict__ v2,
    float* __restrict__ out,                 // (BN, 16, 8)
    int total_bnk)                           // BN * 16
{
    __shared__ float sw[64];                           // folded weights
    __shared__ __align__(16) char xbuf[NWARPS * WB_STRIDE]; // transpose buffers

    int tid = threadIdx.x;

    // In-block BN fold (threads 0..3 -> layer1 rows, 4..11 -> layer2 rows)
    if (tid < 4) {
        float s = g1[tid] * rsqrtf(v1[tid] + LSE_EPS);
        sw[16 + tid] = b1[tid] - m1[tid] * s;
        #pragma unroll
        for (int c = 0; c < 4; ++c) sw[tid * 4 + c] = W1[tid * 4 + c] * s;
    } else if (tid < 12) {
        int j = tid - 4;
        float s = g2[j] * rsqrtf(v2[j] + LSE_EPS);
        sw[52 + j] = b2[j] - m2[j] * s;
        #pragma unroll
        for (int c = 0; c < 4; ++c) sw[20 + j * 4 + c] = W2[j * 4 + c] * s;
    }
    __syncthreads();

    int t = blockIdx.x * blockDim.x + tid;
    if (t >= total_bnk) return;
    int bn = t >> 4;          // point index
    // neighbor index k = t & 15 (implicit in addressing)

    // Register-stage folded weights (broadcast LDS, conflict-free)
    float fw1[16], fb1[4], fw2[32], fb2[8];
    #pragma unroll
    for (int i = 0; i < 16; ++i) fw1[i] = sw[i];
    #pragma unroll
    for (int i = 0; i < 4; ++i)  fb1[i] = sw[16 + i];
    #pragma unroll
    for (int i = 0; i < 32; ++i) fw2[i] = sw[20 + i];
    #pragma unroll
    for (int i = 0; i < 8; ++i)  fb2[i] = sw[52 + i];

    // Loads: neighbor (12B) + center coords (12B, broadcast across 16 lanes)
    const float* np = nbr + (size_t)t * 3;
    const float* cp = coords + (size_t)bn * 3;
    float rx = np[0] - __ldg(cp + 0);
    float ry = np[1] - __ldg(cp + 1);
    float rz = np[2] - __ldg(cp + 2);
    float dist = sqrtf(fmaf(rx, rx, fmaf(ry, ry, rz * rz)));

    // Layer 1: 4x4 + bias + relu
    float h[4];
    #pragma unroll
    for (int o = 0; o < 4; ++o) {
        float acc = fb1[o];
        acc = fmaf(fw1[o * 4 + 0], rx, acc);
        acc = fmaf(fw1[o * 4 + 1], ry, acc);
        acc = fmaf(fw1[o * 4 + 2], rz, acc);
        acc = fmaf(fw1[o * 4 + 3], dist, acc);
        h[o] = fmaxf(acc, 0.0f);
    }

    // Layer 2: 8x4 + bias + relu
    float o8[8];
    #pragma unroll
    for (int j = 0; j < 8; ++j) {
        float acc = fb2[j];
        acc = fmaf(fw2[j * 4 + 0], h[0], acc);
        acc = fmaf(fw2[j * 4 + 1], h[1], acc);
        acc = fmaf(fw2[j * 4 + 2], h[2], acc);
        acc = fmaf(fw2[j * 4 + 3], h[3], acc);
        o8[j] = fmaxf(acc, 0.0f);
    }

    // ---- Warp-local transpose so global stores have 16B lane stride ----
    int warp = tid >> 5;
    int lane = tid & 31;
    char* wb = xbuf + warp * WB_STRIDE;
    float4* A = reinterpret_cast<float4*>(wb);          // first-half chunks (even global chunks)
    float4* B = reinterpret_cast<float4*>(wb + 576);    // second-half chunks (odd global chunks)

    A[lane] = make_float4(o8[0], o8[1], o8[2], o8[3]);  // banks: stride 16B, conflict-free
    B[lane] = make_float4(o8[4], o8[5], o8[6], o8[7]);
    __syncwarp();

    // Global chunk g (16B) of this warp's 1KB output region: g even -> A[g/2], g odd -> B[g/2]
    // Lane l stores chunks l and l+32: fully contiguous lanes within each STG.128.
    int warp_first_bnk = (blockIdx.x * blockDim.x + (warp << 5));
    float4* ob = reinterpret_cast<float4*>(out + (size_t)warp_first_bnk * 8);

    int g0 = lane;           // chunk l
    int g1i = lane + 32;     // chunk l+32
    float4 c0 = (g0 & 1) ? B[g0 >> 1] : A[g0 >> 1];
    float4 c1 = (g1i & 1) ? B[g1i >> 1] : A[g1i >> 1];
    ob[lane]      = c0;
    ob[lane + 32] = c1;
}

extern "C" void kernel_launch(void* const* d_in, const int* in_sizes, int n_in,
                              void* d_out, int out_size)
{
    const float* coords = (const float*)d_in[0];   // (B,N,3)
    const float* nbr    = (const float*)d_in[1];   // (B,N,K,3)
    const float* W1 = (const float*)d_in[2];
    const float* g1 = (const float*)d_in[3];
    const float* b1 = (const float*)d_in[4];
    const float* m1 = (const float*)d_in[5];
    const float* v1 = (const float*)d_in[6];
    const float* W2 = (const float*)d_in[7];
    const float* g2 = (const float*)d_in[8];
    const float* b2 = (const float*)d_in[9];
    const float* m2 = (const float*)d_in[10];
    const float* v2 = (const float*)d_in[11];
    float* out = (float*)d_out;

    int total_bn  = in_sizes[0] / 3;   // B*N
    int total_bnk = total_bn * 16;     // one thread per (bn, k)
    int block = 256;
    int grid = (total_bnk + block - 1) / block;

    lse_fused_kernel<<<grid, block>>>(coords, nbr,
                                      W1, g1, b1, m1, v1,
                                      W2, g2, b2, m2, v2,
                                      out, total_bnk);
}

// round 3
// speedup vs baseline: 1.8150x; 1.3561x over previous
#include <cuda_runtime.h>
#include <math.h>

#define LSE_EPS 1e-5f
#define WARPS_PER_BLOCK 8
#define WB_BYTES 2176        // per-warp transpose/staging buffer (A:0..1023, B:1088..2111)

__global__ __launch_bounds__(256) void lse_fused2_kernel(
    const float* __restrict__ coords,        // (BN, 3)
    const float* __restrict__ nbr,           // (BN, 16, 3)
    const float* __restrict__ W1, const float* __restrict__ g1,
    const float* __restrict__ b1, const float* __restrict__ m1,
    const float* __restrict__ v1,
    const float* __restrict__ W2, const float* __restrict__ g2,
    const float* __restrict__ b2, const float* __restrict__ m2,
    const float* __restrict__ v2,
    float* __restrict__ out,                 // (BN, 16, 8)
    int total_bnk)                           // BN * 16 (pairs)
{
    __shared__ float sw[64];
    __shared__ __align__(16) char buf[WARPS_PER_BLOCK * WB_BYTES];

    int tid = threadIdx.x;

    // In-block BN fold
    if (tid < 4) {
        float s = g1[tid] * rsqrtf(v1[tid] + LSE_EPS);
        sw[16 + tid] = b1[tid] - m1[tid] * s;
        #pragma unroll
        for (int c = 0; c < 4; ++c) sw[tid * 4 + c] = W1[tid * 4 + c] * s;
    } else if (tid < 12) {
        int j = tid - 4;
        float s = g2[j] * rsqrtf(v2[j] + LSE_EPS);
        sw[52 + j] = b2[j] - m2[j] * s;
        #pragma unroll
        for (int c = 0; c < 4; ++c) sw[20 + j * 4 + c] = W2[j * 4 + c] * s;
    }
    __syncthreads();

    int warp = tid >> 5;
    int lane = tid & 31;
    size_t Wg = (size_t)blockIdx.x * WARPS_PER_BLOCK + warp;  // global warp id
    size_t P0 = Wg * 64;                                      // first pair of this warp

    char* wb = buf + warp * WB_BYTES;

    if (P0 + 64 <= (size_t)total_bnk) {
        // ---- Phase 1: cooperative vectorized input staging ----
        float4* st4 = reinterpret_cast<float4*>(wb);
        const float4* nsrc = reinterpret_cast<const float4*>(nbr + P0 * 3);  // 768W bytes, 16B aligned
        st4[lane] = nsrc[lane];
        if (lane < 16) st4[32 + lane] = nsrc[32 + lane];
        float* cdst = reinterpret_cast<float*>(wb) + 192;     // after 48 float4
        const float4* csrc = reinterpret_cast<const float4*>(coords + Wg * 12);  // 48W bytes aligned
        if (lane < 3) reinterpret_cast<float4*>(cdst)[lane] = csrc[lane];
        __syncwarp();

        // ---- Phase 2: read inputs to registers ----
        const float* inF = reinterpret_cast<const float*>(wb);
        int a = lane, b = lane + 32;
        float ax = inF[3 * a], ay = inF[3 * a + 1], az = inF[3 * a + 2];
        float bx = inF[3 * b], by = inF[3 * b + 1], bz = inF[3 * b + 2];
        int pa = a >> 4, pb = b >> 4;
        float cax = cdst[3 * pa], cay = cdst[3 * pa + 1], caz = cdst[3 * pa + 2];
        float cbx = cdst[3 * pb], cby = cdst[3 * pb + 1], cbz = cdst[3 * pb + 2];
        __syncwarp();   // everyone done reading before buffer reused for outputs

        // ---- Phase 3: compute (weights staged; layer1 regs die before layer2) ----
        float fw1[16], fb1[4];
        #pragma unroll
        for (int i = 0; i < 16; ++i) fw1[i] = sw[i];
        #pragma unroll
        for (int i = 0; i < 4; ++i)  fb1[i] = sw[16 + i];

        float rax = ax - cax, ray = ay - cay, raz = az - caz;
        float rbx = bx - cbx, rby = by - cby, rbz = bz - cbz;
        float da = sqrtf(fmaf(rax, rax, fmaf(ray, ray, raz * raz)));
        float db = sqrtf(fmaf(rbx, rbx, fmaf(rby, rby, rbz * rbz)));

        float ha[4], hb[4];
        #pragma unroll
        for (int o = 0; o < 4; ++o) {
            float va = fb1[o], vb = fb1[o];
            va = fmaf(fw1[o * 4 + 0], rax, va);  vb = fmaf(fw1[o * 4 + 0], rbx, vb);
            va = fmaf(fw1[o * 4 + 1], ray, va);  vb = fmaf(fw1[o * 4 + 1], rby, vb);
            va = fmaf(fw1[o * 4 + 2], raz, va);  vb = fmaf(fw1[o * 4 + 2], rbz, vb);
            va = fmaf(fw1[o * 4 + 3], da,  va);  vb = fmaf(fw1[o * 4 + 3], db,  vb);
            ha[o] = fmaxf(va, 0.0f);             hb[o] = fmaxf(vb, 0.0f);
        }

        float4* A4 = reinterpret_cast<float4*>(wb);
        float4* B4 = reinterpret_cast<float4*>(wb + 1088);   // bank offset 16: phases conflict-free

        float oa[8], ob8[8];
        #pragma unroll
        for (int j = 0; j < 8; ++j) {
            float w0 = sw[20 + j * 4 + 0], w1_ = sw[20 + j * 4 + 1];
            float w2_ = sw[20 + j * 4 + 2], w3 = sw[20 + j * 4 + 3];
            float bj = sw[52 + j];
            float va = bj, vb = bj;
            va = fmaf(w0, ha[0], va);  vb = fmaf(w0, hb[0], vb);
            va = fmaf(w1_, ha[1], va); vb = fmaf(w1_, hb[1], vb);
            va = fmaf(w2_, ha[2], va); vb = fmaf(w2_, hb[2], vb);
            va = fmaf(w3, ha[3], va);  vb = fmaf(w3, hb[3], vb);
            oa[j] = fmaxf(va, 0.0f);   ob8[j] = fmaxf(vb, 0.0f);
        }

        A4[a] = make_float4(oa[0], oa[1], oa[2], oa[3]);
        B4[a] = make_float4(oa[4], oa[5], oa[6], oa[7]);
        A4[b] = make_float4(ob8[0], ob8[1], ob8[2], ob8[3]);
        B4[b] = make_float4(ob8[4], ob8[5], ob8[6], ob8[7]);
        __syncwarp();

        // ---- Phase 4: cooperative contiguous stores (lane stride 16B) ----
        float4* obase = reinterpret_cast<float4*>(out + P0 * 8);
        #pragma unroll
        for (int i = 0; i < 4; ++i) {
            int g = lane + 32 * i;
            float4 v = (g & 1) ? B4[g >> 1] : A4[g >> 1];
            obase[g] = v;
        }
    } else {
        // ---- Tail path (not exercised for B=8,N=16384,K=16; kept for safety) ----
        #pragma unroll
        for (int i = 0; i < 2; ++i) {
            size_t p = P0 + lane + 32 * i;
            if (p >= (size_t)total_bnk) continue;
            size_t bn = p >> 4;
            float rx = nbr[p * 3 + 0] - coords[bn * 3 + 0];
            float ry = nbr[p * 3 + 1] - coords[bn * 3 + 1];
            float rz = nbr[p * 3 + 2] - coords[bn * 3 + 2];
            float dist = sqrtf(fmaf(rx, rx, fmaf(ry, ry, rz * rz)));
            float h[4];
            #pragma unroll
            for (int o = 0; o < 4; ++o) {
                float acc = sw[16 + o];
                acc = fmaf(sw[o * 4 + 0], rx, acc);
                acc = fmaf(sw[o * 4 + 1], ry, acc);
                acc = fmaf(sw[o * 4 + 2], rz, acc);
                acc = fmaf(sw[o * 4 + 3], dist, acc);
                h[o] = fmaxf(acc, 0.0f);
            }
            #pragma unroll
            for (int j = 0; j < 8; ++j) {
                float acc = sw[52 + j];
                acc = fmaf(sw[20 + j * 4 + 0], h[0], acc);
                acc = fmaf(sw[20 + j * 4 + 1], h[1], acc);
                acc = fmaf(sw[20 + j * 4 + 2], h[2], acc);
                acc = fmaf(sw[20 + j * 4 + 3], h[3], acc);
                out[p * 8 + j] = fmaxf(acc, 0.0f);
            }
        }
    }
}

extern "C" void kernel_launch(void* const* d_in, const int* in_sizes, int n_in,
                              void* d_out, int out_size)
{
    const float* coords = (const float*)d_in[0];
    const float* nbr    = (const float*)d_in[1];
    const float* W1 = (const float*)d_in[2];
    const float* g1 = (const float*)d_in[3];
    const float* b1 = (const float*)d_in[4];
    const float* m1 = (const float*)d_in[5];
    const float* v1 = (const float*)d_in[6];
    const float* W2 = (const float*)d_in[7];
    const float* g2 = (const float*)d_in[8];
    const float* b2 = (const float*)d_in[9];
    const float* m2 = (const float*)d_in[10];
    const float* v2 = (const float*)d_in[11];
    float* out = (float*)d_out;

    int total_bn  = in_sizes[0] / 3;
    int total_bnk = total_bn * 16;
    int pairs_per_block = 64 * WARPS_PER_BLOCK;   // 512
    int grid = (total_bnk + pairs_per_block - 1) / pairs_per_block;

    lse_fused2_kernel<<<grid, 256>>>(coords, nbr,
                                     W1, g1, b1, m1, v1,
                                     W2, g2, b2, m2, v2,
                                     out, total_bnk);
}